// round 6
// baseline (speedup 1.0000x reference)
#include <cuda_runtime.h>
#include <cuda_fp16.h>
#include <math.h>
#include <stdint.h>

// Problem constants
#define BATCH   8192
#define DMODEL  1024
#define DFF     4096
#define KPATH   4
#define RANK    16
#define HD      512

// ---------------- scratch (device globals; no allocation allowed) ----------
__device__ __half g_W1h[KPATH * DFF * DMODEL];   // [k][4096][1024] (N,K) 32MB
__device__ __half g_W2n[KPATH * DFF * DMODEL];   // [k][4096][1024] natural (d_ff,d_model) 32MB
__device__ __half g_Wfh[KPATH * HD * DFF];       // [k][512][4096] = (W2@hd_in*pw)^T 16MB
__device__ __half g_hdinTh[HD * DMODEL];         // [512][1024]
__device__ __half g_hdoutTh[DMODEL * HD];        // [1024][512]
__device__ __half g_xh[BATCH * DMODEL];          // 16MB
__device__ __half g_h[BATCH * DFF];              // 64MB
__device__ __half g_colh[BATCH * HD];            // 8MB
__device__ float  g_xhd[BATCH * HD];
__device__ float  g_col[BATCH * HD];
__device__ float  g_probs[BATCH * KPATH];

// ---------------- builders / converters -------------------------------------
__global__ void build_w1h(const float* __restrict__ c1a, const float* __restrict__ c1b) {
    int idx = blockIdx.x * blockDim.x + threadIdx.x;
    if (idx >= KPATH * DFF * DMODEL) return;
    int d  = idx & (DMODEL - 1);          // m*32+p  (K index)
    int t  = idx >> 10;
    int nn = t & (DFF - 1);               // n*64+o  (N index)
    int k  = t >> 12;
    int m = d >> 5, p = d & 31;
    int n = nn >> 6, o = nn & 63;
    const float* a = c1a + (((k * 32 + m) * 64 + n) * 16);
    const float* b = c1b + ((size_t)(k * 16) * 32 + p) * 64 + o;
    float s = 0.f;
#pragma unroll
    for (int r = 0; r < RANK; r++) s += a[r] * b[(size_t)r * 32 * 64];
    g_W1h[idx] = __float2half(s);
}

// W2 natural layout: [k][d_ff=4096][d_model=1024], W2[(m*64+p),(n*32+o)]
__global__ void build_w2n(const float* __restrict__ c2a, const float* __restrict__ c2b) {
    int idx = blockIdx.x * blockDim.x + threadIdx.x;
    if (idx >= KPATH * DFF * DMODEL) return;
    int dm = idx & (DMODEL - 1);          // n*32+o
    int t  = idx >> 10;
    int ff = t & (DFF - 1);               // m*64+p
    int k  = t >> 12;
    int n = dm >> 5, o = dm & 31;
    int m = ff >> 6, p = ff & 63;
    const float* a = c2a + (((k * 64 + m) * 32 + n) * 16);
    const float* b = c2b + ((size_t)(k * 16) * 64 + p) * 32 + o;
    float s = 0.f;
#pragma unroll
    for (int r = 0; r < RANK; r++) s += a[r] * b[(size_t)r * 64 * 32];
    g_W2n[idx] = __float2half(s);
}

__global__ void conv_x(const float* __restrict__ x) {
    int i = blockIdx.x * blockDim.x + threadIdx.x;
    if (i < BATCH * DMODEL) g_xh[i] = __float2half(x[i]);
}
__global__ void transpose_hdin(const float* __restrict__ hd_in) {
    int i = blockIdx.x * blockDim.x + threadIdx.x;
    if (i >= DMODEL * HD) return;
    int d = i / HD, h2 = i % HD;
    g_hdinTh[(size_t)h2 * DMODEL + d] = __float2half(hd_in[i]);
}
__global__ void transpose_hdout(const float* __restrict__ hd_out) {
    int i = blockIdx.x * blockDim.x + threadIdx.x;
    if (i >= HD * DMODEL) return;
    int h2 = i / DMODEL, d = i % DMODEL;
    g_hdoutTh[(size_t)d * HD + h2] = __float2half(hd_out[i]);
}
__global__ void conv_col() {
    int i = blockIdx.x * blockDim.x + threadIdx.x;
    if (i < BATCH * HD) g_colh[i] = __float2half(g_col[i]);
}

// ---------------- routing softmax -------------------------------------------
__global__ void routing_kernel(const float* __restrict__ pb) {
    int gid  = blockIdx.x * blockDim.x + threadIdx.x;
    int warp = gid >> 5;
    int lane = gid & 31;
    if (warp >= BATCH) return;
    const float* xr = g_xhd + (size_t)warp * HD;
    float sc[KPATH];
#pragma unroll
    for (int k = 0; k < KPATH; k++) {
        float s = 0.f;
        for (int h = lane; h < HD; h += 32) s += xr[h] * pb[k * HD + h];
#pragma unroll
        for (int off = 16; off; off >>= 1) s += __shfl_xor_sync(0xffffffffu, s, off);
        sc[k] = s;
    }
    if (lane == 0) {
        float mx = fmaxf(fmaxf(sc[0], sc[1]), fmaxf(sc[2], sc[3]));
        float e0 = expf(sc[0] - mx), e1 = expf(sc[1] - mx);
        float e2 = expf(sc[2] - mx), e3 = expf(sc[3] - mx);
        float inv = 1.0f / (e0 + e1 + e2 + e3);
        g_probs[warp * 4 + 0] = e0 * inv;
        g_probs[warp * 4 + 1] = e1 * inv;
        g_probs[warp * 4 + 2] = e2 * inv;
        g_probs[warp * 4 + 3] = e3 * inv;
    }
}

// ---------------- fp16 mma.sync m16n8k16 GEMM --------------------------------
// C[M,N] = A[M,K] @ Bt[N,K]^T. CTA 128x128, BK=64, SW128. 8 warps (4x2), 3 stages.
#define BM 128
#define BN 128
#define BK 64
#define STAGES 3
#define TILEB (BM * 128)
#define STAGEB (2 * TILEB)
#define GEMM_SMEM (STAGES * STAGEB)    // 98304

__device__ __forceinline__ void cp16(uint32_t dst, const void* src) {
    asm volatile("cp.async.cg.shared.global [%0], [%1], 16;"
                 :: "r"(dst), "l"(src) : "memory");
}
__device__ __forceinline__ void cp_commit() {
    asm volatile("cp.async.commit_group;" ::: "memory");
}
template <int N>
__device__ __forceinline__ void cp_wait() {
    asm volatile("cp.async.wait_group %0;" :: "n"(N) : "memory");
}
__device__ __forceinline__ void ldsm4(uint32_t* r, uint32_t addr) {
    asm volatile("ldmatrix.sync.aligned.m8n8.x4.shared.b16 {%0,%1,%2,%3}, [%4];"
                 : "=r"(r[0]), "=r"(r[1]), "=r"(r[2]), "=r"(r[3]) : "r"(addr));
}
__device__ __forceinline__ void mma16816(float* c, const uint32_t* a, const uint32_t* b) {
    asm volatile(
        "mma.sync.aligned.m16n8k16.row.col.f32.f16.f16.f32 "
        "{%0,%1,%2,%3}, {%4,%5,%6,%7}, {%8,%9}, {%0,%1,%2,%3};"
        : "+f"(c[0]), "+f"(c[1]), "+f"(c[2]), "+f"(c[3])
        : "r"(a[0]), "r"(a[1]), "r"(a[2]), "r"(a[3]), "r"(b[0]), "r"(b[1]));
}

__device__ __forceinline__ float gelu_f(float v) {
    float u = 1.5957691216057308f * (v + 0.044715f * v * v * v);
    return v * (1.0f / (1.0f + __expf(-u)));
}

// EPI: 0 = plain, 1 = gelu->half, 2 = probs-scale (+accumulate if kpath>0, fp32 out),
//      3 = pw-row-scale -> half (Wf precompute)
template <int EPI, typename OutT>
__global__ __launch_bounds__(256, 2)
void tgemm(const __half* __restrict__ A, const __half* __restrict__ Bt,
           OutT* __restrict__ C, int M, int N, int Kd,
           const float* __restrict__ pw, int kpath)
{
    extern __shared__ char smem[];
    uint32_t sbase = (uint32_t)__cvta_generic_to_shared(smem);

    int tid  = threadIdx.x;
    int wid  = tid >> 5;
    int lane = tid & 31;
    int g    = lane >> 2;
    int tig  = lane & 3;
    int wm   = wid & 3;
    int wn   = wid >> 2;

    const __half* Ab = A  + (size_t)blockIdx.y * BM * Kd;
    const __half* Bb = Bt + (size_t)blockIdx.x * BN * Kd;
    int KT = Kd / BK;

    float acc[2][8][4];
#pragma unroll
    for (int i = 0; i < 2; i++)
#pragma unroll
        for (int j = 0; j < 8; j++)
#pragma unroll
            for (int q = 0; q < 4; q++) acc[i][j][q] = 0.f;

    uint32_t xm      = (uint32_t)(lane & 7) << 4;
    uint32_t a_row   = (uint32_t)(wm * 32 + (lane & 15)) * 128;
    uint32_t a_klane = (uint32_t)((lane >> 1) & 8) * 2;
    int nlo          = (lane & 7) | ((lane & 16) >> 1);
    uint32_t b_klane = (uint32_t)(lane & 8) * 2;

    auto load_stage = [&](int stage, int kt) {
        uint32_t abase = sbase + stage * STAGEB;
        uint32_t bbase = abase + TILEB;
        const __half* As = Ab + (size_t)kt * BK;
        const __half* Bs = Bb + (size_t)kt * BK;
#pragma unroll
        for (int i = 0; i < 4; i++) {
            int c   = tid + 256 * i;
            int row = c >> 3;
            int ch  = c & 7;
            uint32_t off = (uint32_t)row * 128 + (uint32_t)ch * 16;
            uint32_t sw  = off ^ ((off >> 3) & 0x70);
            cp16(abase + sw, As + (size_t)row * Kd + ch * 8);
            cp16(bbase + sw, Bs + (size_t)row * Kd + ch * 8);
        }
    };

#pragma unroll
    for (int s = 0; s < STAGES - 1; s++) {
        if (s < KT) load_stage(s, s);
        cp_commit();
    }

    for (int kt = 0; kt < KT; kt++) {
        cp_wait<STAGES - 2>();
        __syncthreads();

        int nxt = kt + STAGES - 1;
        if (nxt < KT) load_stage(nxt % STAGES, nxt);
        cp_commit();

        uint32_t abase = sbase + (kt % STAGES) * STAGEB;
        uint32_t bbase = abase + TILEB;

#pragma unroll
        for (int ks = 0; ks < 4; ks++) {
            uint32_t kb = (uint32_t)ks * 32;
            uint32_t af[2][4];
#pragma unroll
            for (int mf = 0; mf < 2; mf++)
                ldsm4(af[mf], abase + a_row + (uint32_t)mf * 16 * 128 +
                                ((kb + a_klane) ^ xm));
            uint32_t bf[4][4];
#pragma unroll
            for (int ng = 0; ng < 4; ng++)
                ldsm4(bf[ng], bbase + (uint32_t)(wn * 64 + ng * 16 + nlo) * 128 +
                                ((kb + b_klane) ^ xm));
#pragma unroll
            for (int mf = 0; mf < 2; mf++)
#pragma unroll
                for (int ng = 0; ng < 4; ng++) {
                    mma16816(acc[mf][2 * ng + 0], af[mf], &bf[ng][0]);
                    mma16816(acc[mf][2 * ng + 1], af[mf], &bf[ng][2]);
                }
        }
        __syncthreads();
    }

    // ---- epilogue ----
#pragma unroll
    for (int mf = 0; mf < 2; mf++) {
        int row0 = blockIdx.y * BM + wm * 32 + mf * 16 + g;
#pragma unroll
        for (int half = 0; half < 2; half++) {
            int row = row0 + half * 8;
            float rs = 1.f;
            if (EPI == 2) rs = g_probs[row * KPATH + kpath];
            if (EPI == 3) rs = pw[kpath * HD + row];
            OutT* Crow = C + (size_t)row * N;
#pragma unroll
            for (int nf = 0; nf < 8; nf++) {
                int col = blockIdx.x * BN + wn * 64 + (nf >> 1) * 16 + (nf & 1) * 8 + 2 * tig;
                float v0 = acc[mf][nf][half * 2 + 0];
                float v1 = acc[mf][nf][half * 2 + 1];
                if (EPI == 1) { v0 = gelu_f(v0); v1 = gelu_f(v1); }
                if (EPI == 2 || EPI == 3) { v0 *= rs; v1 *= rs; }
                if (EPI == 2 && kpath > 0) {
                    v0 += ((const float*)Crow)[col];
                    v1 += ((const float*)Crow)[col + 1];
                }
                if (sizeof(OutT) == 2) {
                    __half2 hv = __floats2half2_rn(v0, v1);
                    *(__half2*)((__half*)Crow + col) = hv;
                } else {
                    *(float2*)((float*)Crow + col) = make_float2(v0, v1);
                }
            }
        }
    }
}

// ---------------- launch -----------------------------------------------------
extern "C" void kernel_launch(void* const* d_in, const int* in_sizes, int n_in,
                              void* d_out, int out_size)
{
    const float* x      = (const float*)d_in[0];
    const float* c1a    = (const float*)d_in[1];
    const float* c1b    = (const float*)d_in[2];
    const float* c2a    = (const float*)d_in[3];
    const float* c2b    = (const float*)d_in[4];
    const float* hd_in  = (const float*)d_in[5];
    const float* hd_out = (const float*)d_in[6];
    const float* pb     = (const float*)d_in[7];
    const float* pw     = (const float*)d_in[8];
    float* out = (float*)d_out;

    __half *W1h, *W2n, *Wfh, *hdinTh, *hdoutTh, *xh, *h, *colh;
    float *xhd, *col;
    cudaGetSymbolAddress((void**)&W1h,     g_W1h);
    cudaGetSymbolAddress((void**)&W2n,     g_W2n);
    cudaGetSymbolAddress((void**)&Wfh,     g_Wfh);
    cudaGetSymbolAddress((void**)&hdinTh,  g_hdinTh);
    cudaGetSymbolAddress((void**)&hdoutTh, g_hdoutTh);
    cudaGetSymbolAddress((void**)&xh,      g_xh);
    cudaGetSymbolAddress((void**)&h,       g_h);
    cudaGetSymbolAddress((void**)&colh,    g_colh);
    cudaGetSymbolAddress((void**)&xhd,     g_xhd);
    cudaGetSymbolAddress((void**)&col,     g_col);

    static bool attr_set = false;
    if (!attr_set) {
        cudaFuncSetAttribute(tgemm<0, float>,  cudaFuncAttributeMaxDynamicSharedMemorySize, GEMM_SMEM);
        cudaFuncSetAttribute(tgemm<1, __half>, cudaFuncAttributeMaxDynamicSharedMemorySize, GEMM_SMEM);
        cudaFuncSetAttribute(tgemm<2, float>,  cudaFuncAttributeMaxDynamicSharedMemorySize, GEMM_SMEM);
        cudaFuncSetAttribute(tgemm<3, __half>, cudaFuncAttributeMaxDynamicSharedMemorySize, GEMM_SMEM);
        attr_set = true;
    }

    // 1. build fp16 operands
    build_w1h<<<(KPATH * DFF * DMODEL + 255) / 256, 256>>>(c1a, c1b);
    build_w2n<<<(KPATH * DFF * DMODEL + 255) / 256, 256>>>(c2a, c2b);
    conv_x<<<(BATCH * DMODEL + 255) / 256, 256>>>(x);
    transpose_hdin<<<(DMODEL * HD + 255) / 256, 256>>>(hd_in);
    transpose_hdout<<<(HD * DMODEL + 255) / 256, 256>>>(hd_out);

    // 2. x_hd = x @ hd_in (fp32, routing input)
    tgemm<0, float><<<dim3(HD / BN, BATCH / BM), 256, GEMM_SMEM>>>(
        xh, hdinTh, xhd, BATCH, HD, DMODEL, nullptr, 0);

    // 3. routing probs
    routing_kernel<<<(BATCH * 32 + 255) / 256, 256>>>(pb);

    // 4. precompute folded tail weights WfT_k[512,4096] = (hd_inT @ W2_k^T) * pw_k(row)
    for (int k = 0; k < KPATH; k++) {
        tgemm<3, __half><<<dim3(DFF / BN, HD / BM), 256, GEMM_SMEM>>>(
            hdinTh, W2n + (size_t)k * DFF * DMODEL,
            Wfh + (size_t)k * HD * DFF, HD, DFF, DMODEL, pw, k);
    }

    // 5. per-path: h = gelu(x@W1_k); col (+)= probs[:,k] * (h @ Wf_k)
    for (int k = 0; k < KPATH; k++) {
        tgemm<1, __half><<<dim3(DFF / BN, BATCH / BM), 256, GEMM_SMEM>>>(
            xh, W1h + (size_t)k * DFF * DMODEL, h, BATCH, DFF, DMODEL, nullptr, 0);
        tgemm<2, float><<<dim3(HD / BN, BATCH / BM), 256, GEMM_SMEM>>>(
            h, Wfh + (size_t)k * HD * DFF, col, BATCH, HD, DFF, nullptr, k);
    }

    // 6. out = col @ hd_out (fp32)
    conv_col<<<(BATCH * HD + 255) / 256, 256>>>();
    tgemm<0, float><<<dim3(DMODEL / BN, BATCH / BM), 256, GEMM_SMEM>>>(
        colh, hdoutTh, out, BATCH, DMODEL, HD, nullptr, 0);
}

// round 8
// speedup vs baseline: 1.6668x; 1.6668x over previous
#include <cuda_runtime.h>
#include <cuda_fp16.h>
#include <math.h>
#include <stdint.h>

// Problem constants
#define BATCH   8192
#define DMODEL  1024
#define DFF     4096
#define KPATH   4
#define RANK    16
#define HD      512

// ---------------- scratch (device globals; no allocation allowed) ----------
__device__ __half g_W1h[KPATH * DFF * DMODEL];   // [k][4096][1024] (N,K) 32MB
__device__ __half g_W2n[KPATH * DFF * DMODEL];   // [k][4096][1024] natural 32MB
__device__ __half g_Wfh[KPATH * HD * DFF];       // [k][512][4096] 16MB
__device__ __half g_hdinTh[HD * DMODEL];
__device__ __half g_hdoutTh[DMODEL * HD];
__device__ __half g_xh[BATCH * DMODEL];          // 16MB
__device__ __half g_h4[(size_t)KPATH * BATCH * DFF];   // 256MB
__device__ float  g_col4[(size_t)KPATH * BATCH * HD];  // 64MB
__device__ __half g_colh[BATCH * HD];            // 8MB
__device__ float  g_xhd[BATCH * HD];
__device__ float  g_probs[BATCH * KPATH];

// ---------------- builders / converters -------------------------------------
__global__ void build_w1h(const float* __restrict__ c1a, const float* __restrict__ c1b) {
    int idx = blockIdx.x * blockDim.x + threadIdx.x;
    if (idx >= KPATH * DFF * DMODEL) return;
    int d  = idx & (DMODEL - 1);
    int t  = idx >> 10;
    int nn = t & (DFF - 1);
    int k  = t >> 12;
    int m = d >> 5, p = d & 31;
    int n = nn >> 6, o = nn & 63;
    const float* a = c1a + (((k * 32 + m) * 64 + n) * 16);
    const float* b = c1b + ((size_t)(k * 16) * 32 + p) * 64 + o;
    float s = 0.f;
#pragma unroll
    for (int r = 0; r < RANK; r++) s += a[r] * b[(size_t)r * 32 * 64];
    g_W1h[idx] = __float2half(s);
}

__global__ void build_w2n(const float* __restrict__ c2a, const float* __restrict__ c2b) {
    int idx = blockIdx.x * blockDim.x + threadIdx.x;
    if (idx >= KPATH * DFF * DMODEL) return;
    int dm = idx & (DMODEL - 1);
    int t  = idx >> 10;
    int ff = t & (DFF - 1);
    int k  = t >> 12;
    int n = dm >> 5, o = dm & 31;
    int m = ff >> 6, p = ff & 63;
    const float* a = c2a + (((k * 64 + m) * 32 + n) * 16);
    const float* b = c2b + ((size_t)(k * 16) * 64 + p) * 32 + o;
    float s = 0.f;
#pragma unroll
    for (int r = 0; r < RANK; r++) s += a[r] * b[(size_t)r * 64 * 32];
    g_W2n[idx] = __float2half(s);
}

__global__ void conv_x(const float* __restrict__ x) {
    int i = blockIdx.x * blockDim.x + threadIdx.x;
    if (i < BATCH * DMODEL) g_xh[i] = __float2half(x[i]);
}
__global__ void transpose_hdin(const float* __restrict__ hd_in) {
    int i = blockIdx.x * blockDim.x + threadIdx.x;
    if (i >= DMODEL * HD) return;
    int d = i / HD, h2 = i % HD;
    g_hdinTh[(size_t)h2 * DMODEL + d] = __float2half(hd_in[i]);
}
__global__ void transpose_hdout(const float* __restrict__ hd_out) {
    int i = blockIdx.x * blockDim.x + threadIdx.x;
    if (i >= HD * DMODEL) return;
    int h2 = i / DMODEL, d = i % DMODEL;
    g_hdoutTh[(size_t)d * HD + h2] = __float2half(hd_out[i]);
}
// sum 4 path partials -> half
__global__ void reduce_col() {
    int i = blockIdx.x * blockDim.x + threadIdx.x;
    if (i >= BATCH * HD) return;
    const size_t SZ = (size_t)BATCH * HD;
    float s = g_col4[i] + g_col4[SZ + i] + g_col4[2 * SZ + i] + g_col4[3 * SZ + i];
    g_colh[i] = __float2half(s);
}

// ---------------- routing softmax -------------------------------------------
__global__ void routing_kernel(const float* __restrict__ pb) {
    int gid  = blockIdx.x * blockDim.x + threadIdx.x;
    int warp = gid >> 5;
    int lane = gid & 31;
    if (warp >= BATCH) return;
    const float* xr = g_xhd + (size_t)warp * HD;
    float sc[KPATH];
#pragma unroll
    for (int k = 0; k < KPATH; k++) {
        float s = 0.f;
        for (int h = lane; h < HD; h += 32) s += xr[h] * pb[k * HD + h];
#pragma unroll
        for (int off = 16; off; off >>= 1) s += __shfl_xor_sync(0xffffffffu, s, off);
        sc[k] = s;
    }
    if (lane == 0) {
        float mx = fmaxf(fmaxf(sc[0], sc[1]), fmaxf(sc[2], sc[3]));
        float e0 = expf(sc[0] - mx), e1 = expf(sc[1] - mx);
        float e2 = expf(sc[2] - mx), e3 = expf(sc[3] - mx);
        float inv = 1.0f / (e0 + e1 + e2 + e3);
        g_probs[warp * 4 + 0] = e0 * inv;
        g_probs[warp * 4 + 1] = e1 * inv;
        g_probs[warp * 4 + 2] = e2 * inv;
        g_probs[warp * 4 + 3] = e3 * inv;
    }
}

// ---------------- fp16 mma.sync m16n8k16 GEMM, z-batched over paths ----------
#define BM 128
#define BN 128
#define BK 64
#define STAGES 3
#define TILEB (BM * 128)
#define STAGEB (2 * TILEB)
#define GEMM_SMEM (STAGES * STAGEB)    // 98304

__device__ __forceinline__ void cp16(uint32_t dst, const void* src) {
    asm volatile("cp.async.cg.shared.global [%0], [%1], 16;"
                 :: "r"(dst), "l"(src) : "memory");
}
__device__ __forceinline__ void cp_commit() {
    asm volatile("cp.async.commit_group;" ::: "memory");
}
template <int N>
__device__ __forceinline__ void cp_wait() {
    asm volatile("cp.async.wait_group %0;" :: "n"(N) : "memory");
}
__device__ __forceinline__ void ldsm4(uint32_t* r, uint32_t addr) {
    asm volatile("ldmatrix.sync.aligned.m8n8.x4.shared.b16 {%0,%1,%2,%3}, [%4];"
                 : "=r"(r[0]), "=r"(r[1]), "=r"(r[2]), "=r"(r[3]) : "r"(addr));
}
__device__ __forceinline__ void mma16816(float* c, const uint32_t* a, const uint32_t* b) {
    asm volatile(
        "mma.sync.aligned.m16n8k16.row.col.f32.f16.f16.f32 "
        "{%0,%1,%2,%3}, {%4,%5,%6,%7}, {%8,%9}, {%0,%1,%2,%3};"
        : "+f"(c[0]), "+f"(c[1]), "+f"(c[2]), "+f"(c[3])
        : "r"(a[0]), "r"(a[1]), "r"(a[2]), "r"(a[3]), "r"(b[0]), "r"(b[1]));
}

__device__ __forceinline__ float gelu_f(float v) {
    float u = 1.5957691216057308f * (v + 0.044715f * v * v * v);
    return v * (1.0f / (1.0f + __expf(-u)));
}

// EPI: 0 = plain, 1 = gelu->half, 2 = probs-scale -> fp32 partial,
//      3 = pw-row-scale -> half (Wf precompute)
// kz = blockIdx.z selects the path; operand/output bases offset by *z strides.
template <int EPI, typename OutT>
__global__ __launch_bounds__(256, 2)
void tgemm(const __half* __restrict__ A, const __half* __restrict__ Bt,
           OutT* __restrict__ C, int M, int N, int Kd,
           const float* __restrict__ pw,
           size_t saz, size_t sbz, size_t scz)
{
    extern __shared__ char smem[];
    uint32_t sbase = (uint32_t)__cvta_generic_to_shared(smem);

    int tid  = threadIdx.x;
    int wid  = tid >> 5;
    int lane = tid & 31;
    int g    = lane >> 2;
    int tig  = lane & 3;
    int wm   = wid & 3;
    int wn   = wid >> 2;
    int kz   = blockIdx.z;

    const __half* Ab = A  + (size_t)kz * saz + (size_t)blockIdx.y * BM * Kd;
    const __half* Bb = Bt + (size_t)kz * sbz + (size_t)blockIdx.x * BN * Kd;
    OutT* Cb = C + (size_t)kz * scz;
    int KT = Kd / BK;

    float acc[2][8][4];
#pragma unroll
    for (int i = 0; i < 2; i++)
#pragma unroll
        for (int j = 0; j < 8; j++)
#pragma unroll
            for (int q = 0; q < 4; q++) acc[i][j][q] = 0.f;

    uint32_t xm      = (uint32_t)(lane & 7) << 4;
    uint32_t a_row   = (uint32_t)(wm * 32 + (lane & 15)) * 128;
    uint32_t a_klane = (uint32_t)((lane >> 1) & 8) * 2;
    int nlo          = (lane & 7) | ((lane & 16) >> 1);
    uint32_t b_klane = (uint32_t)(lane & 8) * 2;

    auto load_stage = [&](int stage, int kt) {
        uint32_t abase = sbase + stage * STAGEB;
        uint32_t bbase = abase + TILEB;
        const __half* As = Ab + (size_t)kt * BK;
        const __half* Bs = Bb + (size_t)kt * BK;
#pragma unroll
        for (int i = 0; i < 4; i++) {
            int c   = tid + 256 * i;
            int row = c >> 3;
            int ch  = c & 7;
            uint32_t off = (uint32_t)row * 128 + (uint32_t)ch * 16;
            uint32_t sw  = off ^ ((off >> 3) & 0x70);
            cp16(abase + sw, As + (size_t)row * Kd + ch * 8);
            cp16(bbase + sw, Bs + (size_t)row * Kd + ch * 8);
        }
    };

#pragma unroll
    for (int s = 0; s < STAGES - 1; s++) {
        if (s < KT) load_stage(s, s);
        cp_commit();
    }

    for (int kt = 0; kt < KT; kt++) {
        cp_wait<STAGES - 2>();
        __syncthreads();

        int nxt = kt + STAGES - 1;
        if (nxt < KT) load_stage(nxt % STAGES, nxt);
        cp_commit();

        uint32_t abase = sbase + (kt % STAGES) * STAGEB;
        uint32_t bbase = abase + TILEB;

#pragma unroll
        for (int ks = 0; ks < 4; ks++) {
            uint32_t kb = (uint32_t)ks * 32;
            uint32_t af[2][4];
#pragma unroll
            for (int mf = 0; mf < 2; mf++)
                ldsm4(af[mf], abase + a_row + (uint32_t)mf * 16 * 128 +
                                ((kb + a_klane) ^ xm));
            uint32_t bf[4][4];
#pragma unroll
            for (int ng = 0; ng < 4; ng++)
                ldsm4(bf[ng], bbase + (uint32_t)(wn * 64 + ng * 16 + nlo) * 128 +
                                ((kb + b_klane) ^ xm));
#pragma unroll
            for (int mf = 0; mf < 2; mf++)
#pragma unroll
                for (int ng = 0; ng < 4; ng++) {
                    mma16816(acc[mf][2 * ng + 0], af[mf], &bf[ng][0]);
                    mma16816(acc[mf][2 * ng + 1], af[mf], &bf[ng][2]);
                }
        }
        __syncthreads();
    }

    // ---- epilogue ----
#pragma unroll
    for (int mf = 0; mf < 2; mf++) {
        int row0 = blockIdx.y * BM + wm * 32 + mf * 16 + g;
#pragma unroll
        for (int half = 0; half < 2; half++) {
            int row = row0 + half * 8;
            float rs = 1.f;
            if (EPI == 2) rs = g_probs[row * KPATH + kz];
            if (EPI == 3) rs = pw[kz * HD + row];
            OutT* Crow = Cb + (size_t)row * N;
#pragma unroll
            for (int nf = 0; nf < 8; nf++) {
                int col = blockIdx.x * BN + wn * 64 + (nf >> 1) * 16 + (nf & 1) * 8 + 2 * tig;
                float v0 = acc[mf][nf][half * 2 + 0];
                float v1 = acc[mf][nf][half * 2 + 1];
                if (EPI == 1) { v0 = gelu_f(v0); v1 = gelu_f(v1); }
                if (EPI == 2 || EPI == 3) { v0 *= rs; v1 *= rs; }
                if (sizeof(OutT) == 2) {
                    __half2 hv = __floats2half2_rn(v0, v1);
                    *(__half2*)((__half*)Crow + col) = hv;
                } else {
                    *(float2*)((float*)Crow + col) = make_float2(v0, v1);
                }
            }
        }
    }
}

// ---------------- launch -----------------------------------------------------
extern "C" void kernel_launch(void* const* d_in, const int* in_sizes, int n_in,
                              void* d_out, int out_size)
{
    const float* x      = (const float*)d_in[0];
    const float* c1a    = (const float*)d_in[1];
    const float* c1b    = (const float*)d_in[2];
    const float* c2a    = (const float*)d_in[3];
    const float* c2b    = (const float*)d_in[4];
    const float* hd_in  = (const float*)d_in[5];
    const float* hd_out = (const float*)d_in[6];
    const float* pb     = (const float*)d_in[7];
    const float* pw     = (const float*)d_in[8];
    float* out = (float*)d_out;

    __half *W1h, *W2n, *Wfh, *hdinTh, *hdoutTh, *xh, *h4, *colh;
    float *xhd, *col4;
    cudaGetSymbolAddress((void**)&W1h,     g_W1h);
    cudaGetSymbolAddress((void**)&W2n,     g_W2n);
    cudaGetSymbolAddress((void**)&Wfh,     g_Wfh);
    cudaGetSymbolAddress((void**)&hdinTh,  g_hdinTh);
    cudaGetSymbolAddress((void**)&hdoutTh, g_hdoutTh);
    cudaGetSymbolAddress((void**)&xh,      g_xh);
    cudaGetSymbolAddress((void**)&h4,      g_h4);
    cudaGetSymbolAddress((void**)&colh,    g_colh);
    cudaGetSymbolAddress((void**)&xhd,     g_xhd);
    cudaGetSymbolAddress((void**)&col4,    g_col4);

    static bool attr_set = false;
    if (!attr_set) {
        cudaFuncSetAttribute(tgemm<0, float>,  cudaFuncAttributeMaxDynamicSharedMemorySize, GEMM_SMEM);
        cudaFuncSetAttribute(tgemm<1, __half>, cudaFuncAttributeMaxDynamicSharedMemorySize, GEMM_SMEM);
        cudaFuncSetAttribute(tgemm<2, float>,  cudaFuncAttributeMaxDynamicSharedMemorySize, GEMM_SMEM);
        cudaFuncSetAttribute(tgemm<3, __half>, cudaFuncAttributeMaxDynamicSharedMemorySize, GEMM_SMEM);
        attr_set = true;
    }

    // 1. build fp16 operands
    build_w1h<<<(KPATH * DFF * DMODEL + 255) / 256, 256>>>(c1a, c1b);
    build_w2n<<<(KPATH * DFF * DMODEL + 255) / 256, 256>>>(c2a, c2b);
    conv_x<<<(BATCH * DMODEL + 255) / 256, 256>>>(x);
    transpose_hdin<<<(DMODEL * HD + 255) / 256, 256>>>(hd_in);
    transpose_hdout<<<(HD * DMODEL + 255) / 256, 256>>>(hd_out);

    // 2. x_hd = x @ hd_in (fp32, routing input)
    tgemm<0, float><<<dim3(HD / BN, BATCH / BM, 1), 256, GEMM_SMEM>>>(
        xh, hdinTh, xhd, BATCH, HD, DMODEL, nullptr, 0, 0, 0);

    // 3. routing probs
    routing_kernel<<<(BATCH * 32 + 255) / 256, 256>>>(pb);

    // 4. folded tail weights, all paths in one launch:
    //    WfT_k[512,4096] = (hd_inT @ W2_k^T) * pw_k(row)
    tgemm<3, __half><<<dim3(DFF / BN, HD / BM, KPATH), 256, GEMM_SMEM>>>(
        hdinTh, W2n, Wfh, HD, DFF, DMODEL, pw,
        0, (size_t)DFF * DMODEL, (size_t)HD * DFF);

    // 5. h_k = gelu(x @ W1_k), all paths in one launch
    tgemm<1, __half><<<dim3(DFF / BN, BATCH / BM, KPATH), 256, GEMM_SMEM>>>(
        xh, W1h, h4, BATCH, DFF, DMODEL, nullptr,
        0, (size_t)DFF * DMODEL, (size_t)BATCH * DFF);

    // 6. col4_k = probs[:,k] * (h_k @ Wf_k), all paths in one launch
    tgemm<2, float><<<dim3(HD / BN, BATCH / BM, KPATH), 256, GEMM_SMEM>>>(
        h4, Wfh, col4, BATCH, HD, DFF, nullptr,
        (size_t)BATCH * DFF, (size_t)HD * DFF, (size_t)BATCH * HD);

    // 7. reduce partials -> colh (fp16)
    reduce_col<<<(BATCH * HD + 255) / 256, 256>>>();

    // 8. out = col @ hd_out (fp32)
    tgemm<0, float><<<dim3(DMODEL / BN, BATCH / BM, 1), 256, GEMM_SMEM>>>(
        colh, hdoutTh, out, BATCH, DMODEL, HD, nullptr, 0, 0, 0);
}